// round 1
// baseline (speedup 1.0000x reference)
#include <cuda_runtime.h>
#include <math.h>

// Problem constants
#define BSZ 2
#define TLEN 2048
#define CDIM 1024
#define HN 16
#define DH 64
#define MROWS (BSZ * TLEN)   // 4096

#define PAD 65               // smem row pad (floats) for conflict-free strided access

// Scratch (allocation-free rule: __device__ globals)
__device__ float g_qkv[(size_t)BSZ * TLEN * 3 * CDIM];  // [B,T,3C]
__device__ float g_y[(size_t)BSZ * TLEN * CDIM];        // [B,T,C]

// ---------------------------------------------------------------------------
// Tiled fp32 GEMM with bias: C[M,N] = A[M,K] @ B[K,N] + bias[N]
// 128x128x16 block tile, 256 threads, 8x8 per-thread microtile.
// mode 0: A = A_param (x), C = g_qkv
// mode 1: A = g_y,        C = C_param (out)
// All dims are multiples of the tile sizes for this problem -> no bounds checks.
// ---------------------------------------------------------------------------
__global__ __launch_bounds__(256) void sgemm_bias_kernel(
    const float* __restrict__ A_param, const float* __restrict__ B,
    const float* __restrict__ bias, float* __restrict__ C_param,
    int M, int N, int K, int mode)
{
    __shared__ float As[16][128];  // transposed A tile: As[k][m]
    __shared__ float Bs[16][128];

    const float* A = (mode == 0) ? A_param : g_y;
    float*       C = (mode == 0) ? g_qkv   : C_param;

    const int tid = threadIdx.x;
    const int n0 = blockIdx.x * 128;
    const int m0 = blockIdx.y * 128;
    const int tx = tid & 15;       // output col group
    const int ty = tid >> 4;       // output row group

    const int arow = tid >> 2;            // 0..63
    const int acol = (tid & 3) << 2;      // 0,4,8,12
    const int brow = tid >> 5;            // 0..7
    const int bcol = (tid & 31) << 2;     // 0..124

    float acc[8][8];
#pragma unroll
    for (int i = 0; i < 8; i++)
#pragma unroll
        for (int j = 0; j < 8; j++) acc[i][j] = 0.f;

    for (int k0 = 0; k0 < K; k0 += 16) {
        float4 a0 = *(const float4*)(A + (size_t)(m0 + arow) * K + k0 + acol);
        float4 a1 = *(const float4*)(A + (size_t)(m0 + arow + 64) * K + k0 + acol);
        float4 b0 = *(const float4*)(B + (size_t)(k0 + brow) * N + n0 + bcol);
        float4 b1 = *(const float4*)(B + (size_t)(k0 + brow + 8) * N + n0 + bcol);

        As[acol + 0][arow] = a0.x; As[acol + 1][arow] = a0.y;
        As[acol + 2][arow] = a0.z; As[acol + 3][arow] = a0.w;
        As[acol + 0][arow + 64] = a1.x; As[acol + 1][arow + 64] = a1.y;
        As[acol + 2][arow + 64] = a1.z; As[acol + 3][arow + 64] = a1.w;
        *(float4*)&Bs[brow][bcol]     = b0;
        *(float4*)&Bs[brow + 8][bcol] = b1;
        __syncthreads();

#pragma unroll
        for (int kk = 0; kk < 16; kk++) {
            float ar[8], br[8];
            *(float4*)(ar)     = *(const float4*)&As[kk][ty * 8];
            *(float4*)(ar + 4) = *(const float4*)&As[kk][ty * 8 + 4];
            *(float4*)(br)     = *(const float4*)&Bs[kk][tx * 8];
            *(float4*)(br + 4) = *(const float4*)&Bs[kk][tx * 8 + 4];
#pragma unroll
            for (int i = 0; i < 8; i++)
#pragma unroll
                for (int j = 0; j < 8; j++) acc[i][j] += ar[i] * br[j];
        }
        __syncthreads();
    }

    float bv[8];
#pragma unroll
    for (int j = 0; j < 8; j++) bv[j] = bias[n0 + tx * 8 + j];

#pragma unroll
    for (int i = 0; i < 8; i++) {
        int row = m0 + ty * 8 + i;
        float* dst = C + (size_t)row * N + n0 + tx * 8;
        float4 r0 = make_float4(acc[i][0] + bv[0], acc[i][1] + bv[1],
                                acc[i][2] + bv[2], acc[i][3] + bv[3]);
        float4 r1 = make_float4(acc[i][4] + bv[4], acc[i][5] + bv[5],
                                acc[i][6] + bv[6], acc[i][7] + bv[7]);
        *(float4*)(dst)     = r0;
        *(float4*)(dst + 4) = r1;
    }
}

// ---------------------------------------------------------------------------
// Flash attention (fp32, online softmax), causal.
// One block per (b, h, 64-query tile). 256 threads = 16x16.
// Thread (ty,tx) owns query rows {ty+16i} and cols {tx+16j} (i,j in 0..3).
// Smem: Qs, Ks, Vs, Ps each 64 x PAD floats (dynamic, 66,560 B).
// ---------------------------------------------------------------------------
__global__ __launch_bounds__(256) void attn_kernel()
{
    extern __shared__ float sm[];
    float* Qs = sm;
    float* Ks = Qs + 64 * PAD;
    float* Vs = Ks + 64 * PAD;
    float* Ps = Vs + 64 * PAD;

    const int qt = blockIdx.x;
    const int h  = blockIdx.y;
    const int b  = blockIdx.z;
    const int tid = threadIdx.x;
    const int tx = tid & 15;
    const int ty = tid >> 4;
    const int q0 = qt * 64;

    const size_t rs = 3 * CDIM;
    const float* qb = g_qkv + (size_t)b * TLEN * rs + h * DH;
    const float* kb = qb + CDIM;
    const float* vb = qb + 2 * CDIM;

    // Load Q tile [64 x 64]
    {
        const int lr = tid >> 4;
        const int lc = (tid & 15) * 4;
#pragma unroll
        for (int p = 0; p < 4; p++) {
            int row = lr + p * 16;
            float4 v4 = *(const float4*)(qb + (size_t)(q0 + row) * rs + lc);
            float* d = Qs + row * PAD + lc;
            d[0] = v4.x; d[1] = v4.y; d[2] = v4.z; d[3] = v4.w;
        }
    }

    float O[16];
    float m[4], l[4];
#pragma unroll
    for (int i = 0; i < 16; i++) O[i] = 0.f;
#pragma unroll
    for (int i = 0; i < 4; i++) { m[i] = -1e30f; l[i] = 0.f; }

    for (int kt = 0; kt <= qt; kt++) {
        __syncthreads();  // protect Vs from prev PV reads; also covers Q load on iter 0
        {
            const int lr = tid >> 4;
            const int lc = (tid & 15) * 4;
            const int k0r = kt * 64;
#pragma unroll
            for (int p = 0; p < 4; p++) {
                int row = lr + p * 16;
                float4 kv = *(const float4*)(kb + (size_t)(k0r + row) * rs + lc);
                float* dk = Ks + row * PAD + lc;
                dk[0] = kv.x; dk[1] = kv.y; dk[2] = kv.z; dk[3] = kv.w;
                float4 vv = *(const float4*)(vb + (size_t)(k0r + row) * rs + lc);
                float* dv = Vs + row * PAD + lc;
                dv[0] = vv.x; dv[1] = vv.y; dv[2] = vv.z; dv[3] = vv.w;
            }
        }
        __syncthreads();

        // S = Q K^T for this tile (4x4 per thread)
        float s[16];
#pragma unroll
        for (int i = 0; i < 16; i++) s[i] = 0.f;
#pragma unroll 16
        for (int d = 0; d < 64; d++) {
            float a[4], bb[4];
#pragma unroll
            for (int i = 0; i < 4; i++) a[i] = Qs[(ty + 16 * i) * PAD + d];
#pragma unroll
            for (int j = 0; j < 4; j++) bb[j] = Ks[(tx + 16 * j) * PAD + d];
#pragma unroll
            for (int i = 0; i < 4; i++)
#pragma unroll
                for (int j = 0; j < 4; j++) s[i * 4 + j] += a[i] * bb[j];
        }

        const float sc = 0.125f;  // 1/sqrt(64)
        if (kt == qt) {
#pragma unroll
            for (int i = 0; i < 4; i++)
#pragma unroll
                for (int j = 0; j < 4; j++)
                    s[i * 4 + j] = (tx + 16 * j > ty + 16 * i) ? -1e30f : s[i * 4 + j] * sc;
        } else {
#pragma unroll
            for (int i = 0; i < 16; i++) s[i] *= sc;
        }

        // Online softmax update per owned row
#pragma unroll
        for (int i = 0; i < 4; i++) {
            float tm = fmaxf(fmaxf(s[i * 4], s[i * 4 + 1]), fmaxf(s[i * 4 + 2], s[i * 4 + 3]));
#pragma unroll
            for (int off = 8; off >= 1; off >>= 1)
                tm = fmaxf(tm, __shfl_xor_sync(0xffffffffu, tm, off));
            float mn = fmaxf(m[i], tm);
            float alpha = __expf(m[i] - mn);
            m[i] = mn;
            float ts = 0.f;
#pragma unroll
            for (int j = 0; j < 4; j++) {
                float p = __expf(s[i * 4 + j] - mn);
                s[i * 4 + j] = p;
                ts += p;
            }
#pragma unroll
            for (int off = 8; off >= 1; off >>= 1)
                ts += __shfl_xor_sync(0xffffffffu, ts, off);
            l[i] = l[i] * alpha + ts;
#pragma unroll
            for (int j = 0; j < 4; j++) O[i * 4 + j] *= alpha;
#pragma unroll
            for (int j = 0; j < 4; j++)
                Ps[(ty + 16 * i) * PAD + tx + 16 * j] = s[i * 4 + j];
        }
        __syncthreads();

        // O += P V  (4x4 per thread; O cols are head-dim cols tx+16j)
#pragma unroll 16
        for (int j64 = 0; j64 < 64; j64++) {
            float a[4], bb[4];
#pragma unroll
            for (int i = 0; i < 4; i++) a[i] = Ps[(ty + 16 * i) * PAD + j64];
#pragma unroll
            for (int j = 0; j < 4; j++) bb[j] = Vs[j64 * PAD + tx + 16 * j];
#pragma unroll
            for (int i = 0; i < 4; i++)
#pragma unroll
                for (int j = 0; j < 4; j++) O[i * 4 + j] += a[i] * bb[j];
        }
    }

    // Normalize and write y[b, q0+r, h*64 + c]
#pragma unroll
    for (int i = 0; i < 4; i++) {
        float inv = 1.f / l[i];
        int row = q0 + ty + 16 * i;
        float* dst = g_y + (size_t)(b * TLEN + row) * CDIM + h * DH;
#pragma unroll
        for (int j = 0; j < 4; j++)
            dst[tx + 16 * j] = O[i * 4 + j] * inv;
    }
}

// ---------------------------------------------------------------------------
extern "C" void kernel_launch(void* const* d_in, const int* in_sizes, int n_in,
                              void* d_out, int out_size)
{
    const float* x      = (const float*)d_in[0];
    const float* W_attn = (const float*)d_in[1];
    const float* b_attn = (const float*)d_in[2];
    const float* W_proj = (const float*)d_in[3];
    const float* b_proj = (const float*)d_in[4];
    float* out = (float*)d_out;

    const size_t attn_smem = (size_t)4 * 64 * PAD * sizeof(float);  // 66,560 B
    cudaFuncSetAttribute(attn_kernel, cudaFuncAttributeMaxDynamicSharedMemorySize,
                         (int)attn_smem);

    // 1) qkv = x @ W_attn + b_attn   (g_qkv)
    {
        dim3 grid((3 * CDIM) / 128, MROWS / 128);
        sgemm_bias_kernel<<<grid, 256>>>(x, W_attn, b_attn, nullptr,
                                         MROWS, 3 * CDIM, CDIM, 0);
    }
    // 2) flash attention -> g_y
    {
        dim3 grid(TLEN / 64, HN, BSZ);
        attn_kernel<<<grid, 256, attn_smem>>>();
    }
    // 3) out = y @ W_proj + b_proj
    {
        dim3 grid(CDIM / 128, MROWS / 128);
        sgemm_bias_kernel<<<grid, 256>>>(nullptr, W_proj, b_proj, out,
                                         MROWS, CDIM, CDIM, 1);
    }
}

// round 2
// speedup vs baseline: 3.3698x; 3.3698x over previous
#include <cuda_runtime.h>
#include <math.h>
#include <stdint.h>

// Problem constants
#define BSZ 2
#define TLEN 2048
#define CDIM 1024
#define HN 16
#define DH 64
#define MROWS (BSZ * TLEN)   // 4096

// Scratch (allocation-free rule: __device__ globals)
__device__ float g_qkv[(size_t)BSZ * TLEN * 3 * CDIM];  // [B,T,3C]
__device__ float g_y[(size_t)BSZ * TLEN * CDIM];        // [B,T,C]

// ---------------------------------------------------------------------------
// tf32 helpers
// ---------------------------------------------------------------------------
__device__ __forceinline__ float to_tf32(float x) {
    uint32_t u;
    asm("cvt.rna.tf32.f32 %0, %1;" : "=r"(u) : "f"(x));
    return __uint_as_float(u);
}

__device__ __forceinline__ void mma_tf32(float* d, const uint32_t* a, const uint32_t* b) {
    asm volatile(
        "mma.sync.aligned.m16n8k8.row.col.f32.tf32.tf32.f32 "
        "{%0,%1,%2,%3}, {%4,%5,%6,%7}, {%8,%9}, {%0,%1,%2,%3};"
        : "+f"(d[0]), "+f"(d[1]), "+f"(d[2]), "+f"(d[3])
        : "r"(a[0]), "r"(a[1]), "r"(a[2]), "r"(a[3]), "r"(b[0]), "r"(b[1]));
}

// ---------------------------------------------------------------------------
// tf32 GEMM with bias: C[M,N] = A[M,K] @ B[K,N] + bias[N]
// 128x128 block tile, BK=32, 256 threads = 8 warps (2m x 4n), each warp 64x32.
// Per warp: 4 m-tiles x 4 n-tiles of m16n8k8.
// mode 0: A = A_param (x), C = g_qkv ; mode 1: A = g_y, C = C_param
// ---------------------------------------------------------------------------
#define SA 36    // As row stride (floats): 36 mod 32 = 4 -> conflict-free a-frag
#define SB 136   // Bs row stride: 136 mod 32 = 8 -> conflict-free b-frag

__global__ __launch_bounds__(256) void gemm_tf32_kernel(
    const float* __restrict__ A_param, const float* __restrict__ B,
    const float* __restrict__ bias, float* __restrict__ C_param,
    int M, int N, int K, int mode)
{
    __shared__ float As[128 * SA];   // [m][k]
    __shared__ float Bs[32 * SB];    // [k][n]

    const float* A = (mode == 0) ? A_param : g_y;
    float*       C = (mode == 0) ? g_qkv   : C_param;

    const int tid  = threadIdx.x;
    const int lane = tid & 31;
    const int wid  = tid >> 5;
    const int wm   = wid >> 2;      // 0..1
    const int wn   = wid & 3;       // 0..3
    const int m0   = blockIdx.y * 128;
    const int n0   = blockIdx.x * 128;

    const int g = lane >> 2;        // group 0..7
    const int q = lane & 3;         // quad 0..3

    // global load assignments
    const int arow = tid >> 3;            // 0..31
    const int ak   = (tid & 7) * 4;       // 0..28
    const int bkr  = tid >> 5;            // 0..7
    const int bn   = (tid & 31) * 4;      // 0..124

    float acc[4][4][4];
#pragma unroll
    for (int mt = 0; mt < 4; mt++)
#pragma unroll
        for (int nt = 0; nt < 4; nt++)
#pragma unroll
            for (int e = 0; e < 4; e++) acc[mt][nt][e] = 0.f;

    // preload chunk 0
    float4 ra[4], rb[4];
#pragma unroll
    for (int p = 0; p < 4; p++) {
        ra[p] = *(const float4*)(A + (size_t)(m0 + arow + 32 * p) * K + ak);
        rb[p] = *(const float4*)(B + (size_t)(bkr + 8 * p) * N + n0 + bn);
    }

    for (int k0 = 0; k0 < K; k0 += 32) {
        // store current chunk to smem (tf32-rounded)
#pragma unroll
        for (int p = 0; p < 4; p++) {
            float* d = &As[(arow + 32 * p) * SA + ak];
            d[0] = to_tf32(ra[p].x); d[1] = to_tf32(ra[p].y);
            d[2] = to_tf32(ra[p].z); d[3] = to_tf32(ra[p].w);
            float* e = &Bs[(bkr + 8 * p) * SB + bn];
            e[0] = to_tf32(rb[p].x); e[1] = to_tf32(rb[p].y);
            e[2] = to_tf32(rb[p].z); e[3] = to_tf32(rb[p].w);
        }
        __syncthreads();

        // prefetch next chunk (global latency overlaps compute)
        if (k0 + 32 < K) {
#pragma unroll
            for (int p = 0; p < 4; p++) {
                ra[p] = *(const float4*)(A + (size_t)(m0 + arow + 32 * p) * K + k0 + 32 + ak);
                rb[p] = *(const float4*)(B + (size_t)(k0 + 32 + bkr + 8 * p) * N + n0 + bn);
            }
        }

#pragma unroll
        for (int kk = 0; kk < 32; kk += 8) {
            uint32_t af[4][4], bf[4][2];
#pragma unroll
            for (int mt = 0; mt < 4; mt++) {
                int r = wm * 64 + mt * 16 + g;
                int c = kk + q;
                af[mt][0] = __float_as_uint(As[r * SA + c]);
                af[mt][1] = __float_as_uint(As[(r + 8) * SA + c]);
                af[mt][2] = __float_as_uint(As[r * SA + c + 4]);
                af[mt][3] = __float_as_uint(As[(r + 8) * SA + c + 4]);
            }
#pragma unroll
            for (int nt = 0; nt < 4; nt++) {
                int c = wn * 32 + nt * 8 + g;
                bf[nt][0] = __float_as_uint(Bs[(kk + q) * SB + c]);
                bf[nt][1] = __float_as_uint(Bs[(kk + 4 + q) * SB + c]);
            }
#pragma unroll
            for (int mt = 0; mt < 4; mt++)
#pragma unroll
                for (int nt = 0; nt < 4; nt++)
                    mma_tf32(acc[mt][nt], af[mt], bf[nt]);
        }
        __syncthreads();
    }

    // epilogue: bias + store (c-frag: rows g, g+8; cols 2q, 2q+1)
#pragma unroll
    for (int mt = 0; mt < 4; mt++) {
        int r0 = m0 + wm * 64 + mt * 16 + g;
#pragma unroll
        for (int nt = 0; nt < 4; nt++) {
            int c = n0 + wn * 32 + nt * 8 + 2 * q;
            float b0 = bias[c], b1 = bias[c + 1];
            *(float2*)(C + (size_t)r0 * N + c) =
                make_float2(acc[mt][nt][0] + b0, acc[mt][nt][1] + b1);
            *(float2*)(C + (size_t)(r0 + 8) * N + c) =
                make_float2(acc[mt][nt][2] + b0, acc[mt][nt][3] + b1);
        }
    }
}

// ---------------------------------------------------------------------------
// Flash attention with tf32 mma. One block per (b, h, 64-query tile).
// 128 threads = 4 warps; warp w owns query rows [w*16, w*16+16).
// S phase: A=Q[16x64], B=K (col-major == K[key][d] row-major) -> S[16x64]
// PV phase: A=P[16x64] (via smem round-trip), B=V^T (Vs[key][d])
// ---------------------------------------------------------------------------
#define SK 68    // Q/K/P row stride: 68 mod 32 = 4
#define SV 72    // V row stride: 72 mod 32 = 8 (key-major b-frag pattern)

__global__ __launch_bounds__(128) void attn_tf32_kernel()
{
    extern __shared__ float sm[];
    float* Qs = sm;                    // [64][SK]
    float* Ks = Qs + 64 * SK;          // [64][SK]
    float* Ps = Ks + 64 * SK;          // [64][SK]
    float* Vs = Ps + 64 * SK;          // [64][SV]

    const int qt = blockIdx.x, h = blockIdx.y, b = blockIdx.z;
    const int tid  = threadIdx.x;
    const int lane = tid & 31;
    const int w    = tid >> 5;
    const int g    = lane >> 2;
    const int q    = lane & 3;
    const int q0   = qt * 64;

    const size_t rs = 3 * CDIM;
    const float* qb = g_qkv + (size_t)b * TLEN * rs + h * DH;
    const float* kb = qb + CDIM;
    const float* vb = qb + 2 * CDIM;

    // Load Q tile (pre-scaled by 1/sqrt(64)=0.125, tf32-rounded)
    {
        const int row = tid >> 4;          // 0..7
        const int col = (tid & 15) * 4;
#pragma unroll
        for (int p = 0; p < 8; p++) {
            float4 v = *(const float4*)(qb + (size_t)(q0 + row + 8 * p) * rs + col);
            float* d = Qs + (row + 8 * p) * SK + col;
            d[0] = to_tf32(v.x * 0.125f); d[1] = to_tf32(v.y * 0.125f);
            d[2] = to_tf32(v.z * 0.125f); d[3] = to_tf32(v.w * 0.125f);
        }
    }

    float so[8][4];                    // O accum: 8 d-tiles x 4 regs
    float mrow[2], lrow[2];
#pragma unroll
    for (int nt = 0; nt < 8; nt++)
#pragma unroll
        for (int e = 0; e < 4; e++) so[nt][e] = 0.f;
    mrow[0] = mrow[1] = -1e30f;
    lrow[0] = lrow[1] = 0.f;

    for (int kt = 0; kt <= qt; kt++) {
        __syncthreads();   // prev PV done before overwriting Ks/Vs
        {
            const int row = tid >> 4;
            const int col = (tid & 15) * 4;
            const int k0r = kt * 64;
#pragma unroll
            for (int p = 0; p < 8; p++) {
                float4 kv = *(const float4*)(kb + (size_t)(k0r + row + 8 * p) * rs + col);
                float* dk = Ks + (row + 8 * p) * SK + col;
                dk[0] = to_tf32(kv.x); dk[1] = to_tf32(kv.y);
                dk[2] = to_tf32(kv.z); dk[3] = to_tf32(kv.w);
                float4 vv = *(const float4*)(vb + (size_t)(k0r + row + 8 * p) * rs + col);
                float* dv = Vs + (row + 8 * p) * SV + col;
                dv[0] = to_tf32(vv.x); dv[1] = to_tf32(vv.y);
                dv[2] = to_tf32(vv.z); dv[3] = to_tf32(vv.w);
            }
        }
        __syncthreads();

        // ---- S = Q K^T (warp: 16 rows x 64 cols) ----
        float sc[8][4];
#pragma unroll
        for (int nt = 0; nt < 8; nt++)
#pragma unroll
            for (int e = 0; e < 4; e++) sc[nt][e] = 0.f;

#pragma unroll
        for (int kk = 0; kk < 64; kk += 8) {
            uint32_t af[4];
            const int r = w * 16 + g;
            af[0] = __float_as_uint(Qs[r * SK + kk + q]);
            af[1] = __float_as_uint(Qs[(r + 8) * SK + kk + q]);
            af[2] = __float_as_uint(Qs[r * SK + kk + 4 + q]);
            af[3] = __float_as_uint(Qs[(r + 8) * SK + kk + 4 + q]);
#pragma unroll
            for (int nt = 0; nt < 8; nt++) {
                uint32_t bf[2];
                const int kn = nt * 8 + g;
                bf[0] = __float_as_uint(Ks[kn * SK + kk + q]);
                bf[1] = __float_as_uint(Ks[kn * SK + kk + 4 + q]);
                mma_tf32(sc[nt], af, bf);
            }
        }

        // ---- causal mask on diagonal tile ----
        if (kt == qt) {
            const int r0 = w * 16 + g, r1 = r0 + 8;
#pragma unroll
            for (int nt = 0; nt < 8; nt++) {
                const int c = nt * 8 + 2 * q;
                if (c     > r0) sc[nt][0] = -1e30f;
                if (c + 1 > r0) sc[nt][1] = -1e30f;
                if (c     > r1) sc[nt][2] = -1e30f;
                if (c + 1 > r1) sc[nt][3] = -1e30f;
            }
        }

        // ---- online softmax for the thread's 2 rows ----
        float mx0 = -1e30f, mx1 = -1e30f;
#pragma unroll
        for (int nt = 0; nt < 8; nt++) {
            mx0 = fmaxf(mx0, fmaxf(sc[nt][0], sc[nt][1]));
            mx1 = fmaxf(mx1, fmaxf(sc[nt][2], sc[nt][3]));
        }
        mx0 = fmaxf(mx0, __shfl_xor_sync(0xffffffffu, mx0, 1));
        mx0 = fmaxf(mx0, __shfl_xor_sync(0xffffffffu, mx0, 2));
        mx1 = fmaxf(mx1, __shfl_xor_sync(0xffffffffu, mx1, 1));
        mx1 = fmaxf(mx1, __shfl_xor_sync(0xffffffffu, mx1, 2));

        const float mn0 = fmaxf(mrow[0], mx0);
        const float mn1 = fmaxf(mrow[1], mx1);
        const float al0 = __expf(mrow[0] - mn0);
        const float al1 = __expf(mrow[1] - mn1);
        mrow[0] = mn0; mrow[1] = mn1;

        float s0 = 0.f, s1 = 0.f;
#pragma unroll
        for (int nt = 0; nt < 8; nt++) {
            sc[nt][0] = __expf(sc[nt][0] - mn0); s0 += sc[nt][0];
            sc[nt][1] = __expf(sc[nt][1] - mn0); s0 += sc[nt][1];
            sc[nt][2] = __expf(sc[nt][2] - mn1); s1 += sc[nt][2];
            sc[nt][3] = __expf(sc[nt][3] - mn1); s1 += sc[nt][3];
        }
        s0 += __shfl_xor_sync(0xffffffffu, s0, 1);
        s0 += __shfl_xor_sync(0xffffffffu, s0, 2);
        s1 += __shfl_xor_sync(0xffffffffu, s1, 1);
        s1 += __shfl_xor_sync(0xffffffffu, s1, 2);
        lrow[0] = lrow[0] * al0 + s0;
        lrow[1] = lrow[1] * al1 + s1;

#pragma unroll
        for (int nt = 0; nt < 8; nt++) {
            so[nt][0] *= al0; so[nt][1] *= al0;
            so[nt][2] *= al1; so[nt][3] *= al1;
        }

        // store P (tf32-rounded) to smem for a-frag reload
        {
            const int r0 = w * 16 + g;
#pragma unroll
            for (int nt = 0; nt < 8; nt++) {
                const int c = nt * 8 + 2 * q;
                *(float2*)&Ps[r0 * SK + c] =
                    make_float2(to_tf32(sc[nt][0]), to_tf32(sc[nt][1]));
                *(float2*)&Ps[(r0 + 8) * SK + c] =
                    make_float2(to_tf32(sc[nt][2]), to_tf32(sc[nt][3]));
            }
        }
        __syncwarp();   // P written by this warp only; reads below are same-warp

        // ---- O += P V ----
#pragma unroll
        for (int kk = 0; kk < 64; kk += 8) {
            uint32_t af[4];
            const int r = w * 16 + g;
            af[0] = __float_as_uint(Ps[r * SK + kk + q]);
            af[1] = __float_as_uint(Ps[(r + 8) * SK + kk + q]);
            af[2] = __float_as_uint(Ps[r * SK + kk + 4 + q]);
            af[3] = __float_as_uint(Ps[(r + 8) * SK + kk + 4 + q]);
#pragma unroll
            for (int nt = 0; nt < 8; nt++) {
                uint32_t bf[2];
                const int d = nt * 8 + g;
                bf[0] = __float_as_uint(Vs[(kk + q) * SV + d]);
                bf[1] = __float_as_uint(Vs[(kk + 4 + q) * SV + d]);
                mma_tf32(so[nt], af, bf);
            }
        }
    }

    // normalize + store y
    {
        const float inv0 = 1.f / lrow[0];
        const float inv1 = 1.f / lrow[1];
        const int r0 = q0 + w * 16 + g;
        float* yb = g_y + (size_t)b * TLEN * CDIM + h * DH;
#pragma unroll
        for (int nt = 0; nt < 8; nt++) {
            const int c = nt * 8 + 2 * q;
            *(float2*)(yb + (size_t)r0 * CDIM + c) =
                make_float2(so[nt][0] * inv0, so[nt][1] * inv0);
            *(float2*)(yb + (size_t)(r0 + 8) * CDIM + c) =
                make_float2(so[nt][2] * inv1, so[nt][3] * inv1);
        }
    }
}

// ---------------------------------------------------------------------------
extern "C" void kernel_launch(void* const* d_in, const int* in_sizes, int n_in,
                              void* d_out, int out_size)
{
    const float* x      = (const float*)d_in[0];
    const float* W_attn = (const float*)d_in[1];
    const float* b_attn = (const float*)d_in[2];
    const float* W_proj = (const float*)d_in[3];
    const float* b_proj = (const float*)d_in[4];
    float* out = (float*)d_out;

    const size_t attn_smem = (size_t)(3 * 64 * SK + 64 * SV) * sizeof(float); // 70,656 B
    cudaFuncSetAttribute(attn_tf32_kernel, cudaFuncAttributeMaxDynamicSharedMemorySize,
                         (int)attn_smem);

    // 1) qkv = x @ W_attn + b_attn
    {
        dim3 grid((3 * CDIM) / 128, MROWS / 128);
        gemm_tf32_kernel<<<grid, 256>>>(x, W_attn, b_attn, nullptr,
                                        MROWS, 3 * CDIM, CDIM, 0);
    }
    // 2) flash attention -> g_y
    {
        dim3 grid(TLEN / 64, HN, BSZ);
        attn_tf32_kernel<<<grid, 128, attn_smem>>>();
    }
    // 3) out = y @ W_proj + b_proj
    {
        dim3 grid(CDIM / 128, MROWS / 128);
        gemm_tf32_kernel<<<grid, 256>>>(nullptr, W_proj, b_proj, out,
                                        MROWS, CDIM, CDIM, 1);
    }
}

// round 5
// speedup vs baseline: 3.5497x; 1.0534x over previous
#include <cuda_runtime.h>
#include <math.h>
#include <stdint.h>

// Problem constants
#define BSZ 2
#define TLEN 2048
#define CDIM 1024
#define HN 16
#define DH 64
#define MROWS (BSZ * TLEN)   // 4096

// Scratch (allocation-free rule: __device__ globals)
__device__ float g_qkv[(size_t)MROWS * 3 * CDIM];   // tf32 values
__device__ float g_y[(size_t)MROWS * CDIM];         // tf32 values
__device__ float g_xc[(size_t)MROWS * CDIM];        // tf32(x)
__device__ float g_wt[(size_t)4 * CDIM * CDIM];     // tf32(W_attn^T), tf32(W_proj^T)

// ---------------------------------------------------------------------------
// helpers
// ---------------------------------------------------------------------------
__device__ __forceinline__ float to_tf32(float x) {
    uint32_t u;
    asm("cvt.rna.tf32.f32 %0, %1;" : "=r"(u) : "f"(x));
    return __uint_as_float(u);
}

__device__ __forceinline__ void mma_tf32(float* d, const uint32_t* a, const uint32_t* b) {
    asm volatile(
        "mma.sync.aligned.m16n8k8.row.col.f32.tf32.tf32.f32 "
        "{%0,%1,%2,%3}, {%4,%5,%6,%7}, {%8,%9}, {%0,%1,%2,%3};"
        : "+f"(d[0]), "+f"(d[1]), "+f"(d[2]), "+f"(d[3])
        : "r"(a[0]), "r"(a[1]), "r"(a[2]), "r"(a[3]), "r"(b[0]), "r"(b[1]));
}

__device__ __forceinline__ uint32_t smem_u32(const void* p) {
    uint32_t a;
    asm("{ .reg .u64 t; cvta.to.shared.u64 t, %1; cvt.u32.u64 %0, t; }"
        : "=r"(a) : "l"(p));
    return a;
}

__device__ __forceinline__ void ldsm_x4(uint32_t* r, uint32_t addr) {
    asm volatile("ldmatrix.sync.aligned.m8n8.x4.shared.b16 {%0,%1,%2,%3}, [%4];"
                 : "=r"(r[0]), "=r"(r[1]), "=r"(r[2]), "=r"(r[3]) : "r"(addr));
}

// a-frag (16x8, [m][k] smem): reg i = mat i; mats: (mlo,klo),(mhi,klo),(mlo,khi),(mhi,khi)
__device__ __forceinline__ uint32_t a_frag_off(int lane, int stride) {
    int mat = lane >> 3, rw = lane & 7;
    return (uint32_t)(((8 * (mat & 1) + rw) * stride + 4 * (mat >> 1)) * 4);
}
// b-frag pair (2 n-tiles, [n][k] smem): mats: (nt0,klo),(nt0,khi),(nt1,klo),(nt1,khi)
__device__ __forceinline__ uint32_t b_frag_off(int lane, int stride) {
    int mat = lane >> 3, rw = lane & 7;
    return (uint32_t)(((8 * (mat >> 1) + rw) * stride + 4 * (mat & 1)) * 4);
}

#define CP16(s, g) \
    asm volatile("cp.async.cg.shared.global [%0], [%1], 16;" :: "r"(s), "l"(g) : "memory")
#define CP_COMMIT() asm volatile("cp.async.commit_group;" ::: "memory")
#define CP_WAIT(n)  asm volatile("cp.async.wait_group %0;" :: "n"(n) : "memory")

// ---------------------------------------------------------------------------
// x -> tf32 conversion
// ---------------------------------------------------------------------------
__global__ __launch_bounds__(256) void cvt_kernel(const float* __restrict__ x)
{
    size_t i = ((size_t)blockIdx.x * 256 + threadIdx.x) * 4;
    float4 v = *(const float4*)(x + i);
    *(float4*)(g_xc + i) = make_float4(to_tf32(v.x), to_tf32(v.y),
                                       to_tf32(v.z), to_tf32(v.w));
}

// ---------------------------------------------------------------------------
// Weight transpose + tf32: src[K][N] -> g_wt(+off)[N][K]
// ---------------------------------------------------------------------------
__global__ __launch_bounds__(256) void transpose_kernel(
    const float* __restrict__ src, int K, int N, int sel)
{
    __shared__ float t[32][33];
    float* dst = g_wt + (sel ? (size_t)3 * CDIM * CDIM : 0);
    const int nb = blockIdx.x * 32, kb = blockIdx.y * 32;
    const int x = threadIdx.x, y = threadIdx.y;
#pragma unroll
    for (int j = 0; j < 32; j += 8)
        t[y + j][x] = src[(size_t)(kb + y + j) * N + nb + x];
    __syncthreads();
#pragma unroll
    for (int j = 0; j < 32; j += 8)
        dst[(size_t)(nb + y + j) * K + kb + x] = to_tf32(t[x][y + j]);
}

// ---------------------------------------------------------------------------
// tf32 GEMM via ldmatrix + cp.async double buffer.
// C[M,N] = A[M,K] @ W[K,N] + bias[N]; W via pre-transposed g_wt[N][K].
// 128x128 tile, BK=32, 256 threads = 8 warps (2m x 4n), warp 64x32.
// mode 0: A=g_xc, C=g_qkv (tf32-rounded store); mode 1: A=g_y, C=C_param.
// ---------------------------------------------------------------------------
#define SA 36                    // smem stride (floats); 36*4=144B (16B mult), 9 chunks -> LDSM conflict-free
#define ABYTES (128 * SA * 4)    // 18432 per A (or B) tile
#define BUFBYTES (2 * ABYTES)    // 36864 per stage
#define GSMEM (2 * BUFBYTES)     // 73728

__global__ __launch_bounds__(256) void gemm_ls_kernel(
    const float* __restrict__ bias, float* __restrict__ C_param,
    int M, int N, int K, int mode)
{
    extern __shared__ float smg[];
    const float* A  = mode ? g_y : g_xc;
    const float* Bt = g_wt + (mode ? (size_t)3 * CDIM * CDIM : 0);
    float*       C  = mode ? C_param : g_qkv;

    const int tid = threadIdx.x, lane = tid & 31, wid = tid >> 5;
    const int wm = wid >> 2, wn = wid & 3;
    const int g = lane >> 2, q = lane & 3;
    const int m0 = blockIdx.y * 128, n0 = blockIdx.x * 128;
    const uint32_t sb = smem_u32(smg);

    const int row0 = tid >> 3, c4 = tid & 7;
    const uint32_t s_off = (uint32_t)((row0 * SA + c4 * 4) * 4);
    const uint32_t a_off = a_frag_off(lane, SA);
    const uint32_t b_off = b_frag_off(lane, SA);

    float acc[4][4][4];
#pragma unroll
    for (int mt = 0; mt < 4; mt++)
#pragma unroll
        for (int nt = 0; nt < 4; nt++)
#pragma unroll
            for (int e = 0; e < 4; e++) acc[mt][nt][e] = 0.f;

    // prefetch chunk 0
#pragma unroll
    for (int i = 0; i < 4; i++) {
        uint32_t sa = sb + s_off + (uint32_t)(32 * i * SA * 4);
        CP16(sa, A + (size_t)(m0 + row0 + 32 * i) * K + c4 * 4);
        CP16(sa + ABYTES, Bt + (size_t)(n0 + row0 + 32 * i) * K + c4 * 4);
    }
    CP_COMMIT();

    const int nc = K / 32;
    for (int c = 0; c < nc; c++) {
        if (c + 1 < nc) {
            const int k0 = (c + 1) * 32;
            const uint32_t bb = (uint32_t)(((c + 1) & 1) * BUFBYTES);
#pragma unroll
            for (int i = 0; i < 4; i++) {
                uint32_t sa = sb + bb + s_off + (uint32_t)(32 * i * SA * 4);
                CP16(sa, A + (size_t)(m0 + row0 + 32 * i) * K + k0 + c4 * 4);
                CP16(sa + ABYTES, Bt + (size_t)(n0 + row0 + 32 * i) * K + k0 + c4 * 4);
            }
            CP_COMMIT();
            CP_WAIT(1);
        } else {
            CP_WAIT(0);
        }
        __syncthreads();

        const uint32_t ab = sb + (uint32_t)((c & 1) * BUFBYTES);
        const uint32_t bbse = ab + ABYTES;
#pragma unroll
        for (int kk = 0; kk < 32; kk += 8) {
            uint32_t af[4][4], bf[2][4];
#pragma unroll
            for (int mt = 0; mt < 4; mt++)
                ldsm_x4(af[mt], ab + (uint32_t)(((wm * 64 + mt * 16) * SA + kk) * 4) + a_off);
#pragma unroll
            for (int pr = 0; pr < 2; pr++)
                ldsm_x4(bf[pr], bbse + (uint32_t)(((wn * 32 + pr * 16) * SA + kk) * 4) + b_off);
#pragma unroll
            for (int mt = 0; mt < 4; mt++)
#pragma unroll
                for (int nt = 0; nt < 4; nt++)
                    mma_tf32(acc[mt][nt], af[mt], bf[nt >> 1] + (nt & 1) * 2);
        }
        __syncthreads();
    }

    // epilogue
#pragma unroll
    for (int mt = 0; mt < 4; mt++) {
        int r0 = m0 + wm * 64 + mt * 16 + g;
#pragma unroll
        for (int nt = 0; nt < 4; nt++) {
            int cc = n0 + wn * 32 + nt * 8 + 2 * q;
            float b0 = bias[cc], b1 = bias[cc + 1];
            float v00 = acc[mt][nt][0] + b0, v01 = acc[mt][nt][1] + b1;
            float v10 = acc[mt][nt][2] + b0, v11 = acc[mt][nt][3] + b1;
            if (mode == 0) {
                v00 = to_tf32(v00); v01 = to_tf32(v01);
                v10 = to_tf32(v10); v11 = to_tf32(v11);
            }
            *(float2*)(C + (size_t)r0 * N + cc)       = make_float2(v00, v01);
            *(float2*)(C + (size_t)(r0 + 8) * N + cc) = make_float2(v10, v11);
        }
    }
}

// ---------------------------------------------------------------------------
// Flash attention, tf32 mma + ldmatrix fragments.
// One block per (b, h, 64-query tile); 128 threads = 4 warps (16 rows each).
// qkv already tf32. Q frags preloaded + scaled by 0.125 (exact).
// V transposed in smem (Vt[d][key]) so PV b-frags are ldmatrix too.
// ---------------------------------------------------------------------------
#define SKA 68                       // stride (floats): 272B (16B mult), 17 chunks -> LDSM conflict-free
#define TILE_F (64 * SKA)            // floats per tile
#define TILE_B (TILE_F * 4)          // 17408 bytes
#define ASMEM (5 * TILE_B)           // Q,K,P,Vs,Vt = 87040

__global__ __launch_bounds__(128) void attn_ls_kernel()
{
    extern __shared__ float sm[];
    float* Qs = sm;
    float* Ks = Qs + TILE_F;
    float* Ps = Ks + TILE_F;
    float* Vs = Ps + TILE_F;
    float* Vt = Vs + TILE_F;

    const int qt = blockIdx.x, h = blockIdx.y, b = blockIdx.z;
    const int tid = threadIdx.x, lane = tid & 31, w = tid >> 5;
    const int g = lane >> 2, q = lane & 3;
    const int q0 = qt * 64;

    const uint32_t sb  = smem_u32(sm);
    const uint32_t sQ = sb, sK = sb + TILE_B, sP = sb + 2 * TILE_B, sVt = sb + 4 * TILE_B;

    const size_t rs = 3 * CDIM;
    const float* qb = g_qkv + (size_t)b * TLEN * rs + h * DH;
    const float* kb = qb + CDIM;
    const float* vb = qb + 2 * CDIM;

    const int lrow = tid >> 4;             // 0..7
    const int lcol = (tid & 15) * 4;       // 0..60
    const uint32_t aoff = a_frag_off(lane, SKA);
    const uint32_t boff = b_frag_off(lane, SKA);

    // ---- load Q (cp.async), preload+scale fragments ----
#pragma unroll
    for (int p = 0; p < 8; p++) {
        uint32_t d = sQ + (uint32_t)(((lrow + 8 * p) * SKA + lcol) * 4);
        CP16(d, qb + (size_t)(q0 + lrow + 8 * p) * rs + lcol);
    }
    CP_COMMIT(); CP_WAIT(0);
    __syncthreads();

    uint32_t qf[8][4];
#pragma unroll
    for (int kd = 0; kd < 8; kd++) {
        ldsm_x4(qf[kd], sQ + (uint32_t)(((w * 16) * SKA + kd * 8) * 4) + aoff);
#pragma unroll
        for (int e = 0; e < 4; e++)
            qf[kd][e] = __float_as_uint(__uint_as_float(qf[kd][e]) * 0.125f);
    }

    float so[8][4];
    float mrow[2] = {-1e30f, -1e30f}, lsum[2] = {0.f, 0.f};
#pragma unroll
    for (int nt = 0; nt < 8; nt++)
#pragma unroll
        for (int e = 0; e < 4; e++) so[nt][e] = 0.f;

    for (int kt = 0; kt <= qt; kt++) {
        __syncthreads();   // prior S/PV reads of Ks/Vt done
        {
            const int k0r = kt * 64;
#pragma unroll
            for (int p = 0; p < 8; p++) {
                uint32_t dk = sK + (uint32_t)(((lrow + 8 * p) * SKA + lcol) * 4);
                CP16(dk, kb + (size_t)(k0r + lrow + 8 * p) * rs + lcol);
                CP16(dk + 2 * TILE_B, vb + (size_t)(k0r + lrow + 8 * p) * rs + lcol); // -> Vs
            }
            CP_COMMIT(); CP_WAIT(0);
        }
        __syncthreads();

        // ---- transpose V: Vs[key][d] -> Vt[d][key] (conflict-free) ----
        {
            const int td = tid & 63, tk = (tid >> 6) * 32;
#pragma unroll
            for (int i = 0; i < 8; i++) {
                const int k0 = tk + 4 * i;
                float4 v;
                v.x = Vs[(k0 + 0) * SKA + td];
                v.y = Vs[(k0 + 1) * SKA + td];
                v.z = Vs[(k0 + 2) * SKA + td];
                v.w = Vs[(k0 + 3) * SKA + td];
                *(float4*)&Vt[td * SKA + k0] = v;
            }
        }
        __syncthreads();

        // ---- S = Q K^T ----
        float sc[8][4];
#pragma unroll
        for (int nt = 0; nt < 8; nt++)
#pragma unroll
            for (int e = 0; e < 4; e++) sc[nt][e] = 0.f;

#pragma unroll
        for (int kd = 0; kd < 8; kd++) {
            uint32_t bf[4][4];
#pragma unroll
            for (int pr = 0; pr < 4; pr++)
                ldsm_x4(bf[pr], sK + (uint32_t)(((pr * 16) * SKA + kd * 8) * 4) + boff);
#pragma unroll
            for (int nt = 0; nt < 8; nt++)
                mma_tf32(sc[nt], qf[kd], bf[nt >> 1] + (nt & 1) * 2);
        }

        // ---- causal mask on diagonal tile ----
        if (kt == qt) {
            const int r0 = w * 16 + g, r1 = r0 + 8;
#pragma unroll
            for (int nt = 0; nt < 8; nt++) {
                const int c = nt * 8 + 2 * q;
                if (c     > r0) sc[nt][0] = -1e30f;
                if (c + 1 > r0) sc[nt][1] = -1e30f;
                if (c     > r1) sc[nt][2] = -1e30f;
                if (c + 1 > r1) sc[nt][3] = -1e30f;
            }
        }

        // ---- online softmax (2 rows per thread) ----
        float mx0 = -1e30f, mx1 = -1e30f;
#pragma unroll
        for (int nt = 0; nt < 8; nt++) {
            mx0 = fmaxf(mx0, fmaxf(sc[nt][0], sc[nt][1]));
            mx1 = fmaxf(mx1, fmaxf(sc[nt][2], sc[nt][3]));
        }
        mx0 = fmaxf(mx0, __shfl_xor_sync(0xffffffffu, mx0, 1));
        mx0 = fmaxf(mx0, __shfl_xor_sync(0xffffffffu, mx0, 2));
        mx1 = fmaxf(mx1, __shfl_xor_sync(0xffffffffu, mx1, 1));
        mx1 = fmaxf(mx1, __shfl_xor_sync(0xffffffffu, mx1, 2));

        const float mn0 = fmaxf(mrow[0], mx0);
        const float mn1 = fmaxf(mrow[1], mx1);
        const float al0 = __expf(mrow[0] - mn0);
        const float al1 = __expf(mrow[1] - mn1);
        mrow[0] = mn0; mrow[1] = mn1;

        float s0 = 0.f, s1 = 0.f;
#pragma unroll
        for (int nt = 0; nt < 8; nt++) {
            sc[nt][0] = __expf(sc[nt][0] - mn0); s0 += sc[nt][0];
            sc[nt][1] = __expf(sc[nt][1] - mn0); s0 += sc[nt][1];
            sc[nt][2] = __expf(sc[nt][2] - mn1); s1 += sc[nt][2];
            sc[nt][3] = __expf(sc[nt][3] - mn1); s1 += sc[nt][3];
        }
        s0 += __shfl_xor_sync(0xffffffffu, s0, 1);
        s0 += __shfl_xor_sync(0xffffffffu, s0, 2);
        s1 += __shfl_xor_sync(0xffffffffu, s1, 1);
        s1 += __shfl_xor_sync(0xffffffffu, s1, 2);
        lsum[0] = lsum[0] * al0 + s0;
        lsum[1] = lsum[1] * al1 + s1;

#pragma unroll
        for (int nt = 0; nt < 8; nt++) {
            so[nt][0] *= al0; so[nt][1] *= al0;
            so[nt][2] *= al1; so[nt][3] *= al1;
        }

        // ---- store P (tf32) for a-frag reload ----
        {
            const int r0 = w * 16 + g;
#pragma unroll
            for (int nt = 0; nt < 8; nt++) {
                const int c = nt * 8 + 2 * q;
                *(float2*)&Ps[r0 * SKA + c] =
                    make_float2(to_tf32(sc[nt][0]), to_tf32(sc[nt][1]));
                *(float2*)&Ps[(r0 + 8) * SKA + c] =
                    make_float2(to_tf32(sc[nt][2]), to_tf32(sc[nt][3]));
            }
        }
        __syncwarp();   // P rows owned/read by this warp only

        // ---- O += P V ----
#pragma unroll
        for (int kd = 0; kd < 8; kd++) {
            uint32_t pf[4], bf[4][4];
            ldsm_x4(pf, sP + (uint32_t)(((w * 16) * SKA + kd * 8) * 4) + aoff);
#pragma unroll
            for (int pr = 0; pr < 4; pr++)
                ldsm_x4(bf[pr], sVt + (uint32_t)(((pr * 16) * SKA + kd * 8) * 4) + boff);
#pragma unroll
            for (int nt = 0; nt < 8; nt++)
                mma_tf32(so[nt], pf, bf[nt >> 1] + (nt & 1) * 2);
        }
    }

    // ---- normalize + store y (tf32 for GEMM2 consumption) ----
    {
        const float inv0 = 1.f / lsum[0];
        const float inv1 = 1.f / lsum[1];
        const int r0 = q0 + w * 16 + g;
        float* yb = g_y + (size_t)b * TLEN * CDIM + h * DH;
#pragma unroll
        for (int nt = 0; nt < 8; nt++) {
            const int c = nt * 8 + 2 * q;
            *(float2*)(yb + (size_t)r0 * CDIM + c) =
                make_float2(to_tf32(so[nt][0] * inv0), to_tf32(so[nt][1] * inv0));
            *(float2*)(yb + (size_t)(r0 + 8) * CDIM + c) =
                make_float2(to_tf32(so[nt][2] * inv1), to_tf32(so[nt][3] * inv1));
        }
    }
}

// ---------------------------------------------------------------------------
extern "C" void kernel_launch(void* const* d_in, const int* in_sizes, int n_in,
                              void* d_out, int out_size)
{
    const float* x      = (const float*)d_in[0];
    const float* W_attn = (const float*)d_in[1];
    const float* b_attn = (const float*)d_in[2];
    const float* W_proj = (const float*)d_in[3];
    const float* b_proj = (const float*)d_in[4];
    float* out = (float*)d_out;

    cudaFuncSetAttribute(gemm_ls_kernel, cudaFuncAttributeMaxDynamicSharedMemorySize, GSMEM);
    cudaFuncSetAttribute(attn_ls_kernel, cudaFuncAttributeMaxDynamicSharedMemorySize, ASMEM);

    // 0) pre-convert x; transpose+convert weights
    cvt_kernel<<<(MROWS * CDIM) / (256 * 4), 256>>>(x);
    {
        dim3 tb(32, 8);
        transpose_kernel<<<dim3((3 * CDIM) / 32, CDIM / 32), tb>>>(W_attn, CDIM, 3 * CDIM, 0);
        transpose_kernel<<<dim3(CDIM / 32, CDIM / 32), tb>>>(W_proj, CDIM, CDIM, 1);
    }
    // 1) qkv = x @ W_attn + b_attn (tf32-rounded)
    {
        dim3 grid((3 * CDIM) / 128, MROWS / 128);
        gemm_ls_kernel<<<grid, 256, GSMEM>>>(b_attn, nullptr, MROWS, 3 * CDIM, CDIM, 0);
    }
    // 2) flash attention -> g_y (tf32-rounded)
    {
        dim3 grid(TLEN / 64, HN, BSZ);
        attn_ls_kernel<<<grid, 128, ASMEM>>>();
    }
    // 3) out = y @ W_proj + b_proj
    {
        dim3 grid(CDIM / 128, MROWS / 128);
        gemm_ls_kernel<<<grid, 256, GSMEM>>>(b_proj, out, MROWS, CDIM, CDIM, 1);
    }
}

// round 6
// speedup vs baseline: 3.7526x; 1.0572x over previous
#include <cuda_runtime.h>
#include <math.h>
#include <stdint.h>

// Problem constants
#define BSZ 2
#define TLEN 2048
#define CDIM 1024
#define HN 16
#define DH 64
#define MROWS (BSZ * TLEN)   // 4096

// Scratch (allocation-free rule: __device__ globals)
__device__ float g_qkv[(size_t)MROWS * 3 * CDIM];   // tf32 values
__device__ float g_y[(size_t)MROWS * CDIM];         // tf32 values
__device__ float g_xc[(size_t)MROWS * CDIM];        // tf32(x)
__device__ float g_wt[(size_t)4 * CDIM * CDIM];     // tf32(W_attn^T), tf32(W_proj^T)

// ---------------------------------------------------------------------------
// helpers
// ---------------------------------------------------------------------------
__device__ __forceinline__ float to_tf32(float x) {
    uint32_t u;
    asm("cvt.rna.tf32.f32 %0, %1;" : "=r"(u) : "f"(x));
    return __uint_as_float(u);
}

__device__ __forceinline__ void mma_tf32(float* d, const uint32_t* a, const uint32_t* b) {
    asm volatile(
        "mma.sync.aligned.m16n8k8.row.col.f32.tf32.tf32.f32 "
        "{%0,%1,%2,%3}, {%4,%5,%6,%7}, {%8,%9}, {%0,%1,%2,%3};"
        : "+f"(d[0]), "+f"(d[1]), "+f"(d[2]), "+f"(d[3])
        : "r"(a[0]), "r"(a[1]), "r"(a[2]), "r"(a[3]), "r"(b[0]), "r"(b[1]));
}

__device__ __forceinline__ uint32_t smem_u32(const void* p) {
    uint32_t a;
    asm("{ .reg .u64 t; cvta.to.shared.u64 t, %1; cvt.u32.u64 %0, t; }"
        : "=r"(a) : "l"(p));
    return a;
}

__device__ __forceinline__ void ldsm_x4(uint32_t* r, uint32_t addr) {
    asm volatile("ldmatrix.sync.aligned.m8n8.x4.shared.b16 {%0,%1,%2,%3}, [%4];"
                 : "=r"(r[0]), "=r"(r[1]), "=r"(r[2]), "=r"(r[3]) : "r"(addr));
}

// a-frag (16x8, [m][k] smem): mats: (mlo,klo),(mhi,klo),(mlo,khi),(mhi,khi)
__device__ __forceinline__ uint32_t a_frag_off(int lane, int stride) {
    int mat = lane >> 3, rw = lane & 7;
    return (uint32_t)(((8 * (mat & 1) + rw) * stride + 4 * (mat >> 1)) * 4);
}
// b-frag pair (2 n-tiles, [n][k] smem): mats: (nt0,klo),(nt0,khi),(nt1,klo),(nt1,khi)
__device__ __forceinline__ uint32_t b_frag_off(int lane, int stride) {
    int mat = lane >> 3, rw = lane & 7;
    return (uint32_t)(((8 * (mat >> 1) + rw) * stride + 4 * (mat & 1)) * 4);
}

#define CP16(s, g) \
    asm volatile("cp.async.cg.shared.global [%0], [%1], 16;" :: "r"(s), "l"(g) : "memory")
#define CP_COMMIT() asm volatile("cp.async.commit_group;" ::: "memory")
#define CP_WAIT(n)  asm volatile("cp.async.wait_group %0;" :: "n"(n) : "memory")

// ---------------------------------------------------------------------------
// x -> tf32 conversion
// ---------------------------------------------------------------------------
__global__ __launch_bounds__(256) void cvt_kernel(const float* __restrict__ x)
{
    size_t i = ((size_t)blockIdx.x * 256 + threadIdx.x) * 4;
    float4 v = *(const float4*)(x + i);
    *(float4*)(g_xc + i) = make_float4(to_tf32(v.x), to_tf32(v.y),
                                       to_tf32(v.z), to_tf32(v.w));
}

// ---------------------------------------------------------------------------
// Weight transpose + tf32: src[K][N] -> g_wt(+off)[N][K]
// ---------------------------------------------------------------------------
__global__ __launch_bounds__(256) void transpose_kernel(
    const float* __restrict__ src, int K, int N, int sel)
{
    __shared__ float t[32][33];
    float* dst = g_wt + (sel ? (size_t)3 * CDIM * CDIM : 0);
    const int nb = blockIdx.x * 32, kb = blockIdx.y * 32;
    const int x = threadIdx.x, y = threadIdx.y;
#pragma unroll
    for (int j = 0; j < 32; j += 8)
        t[y + j][x] = src[(size_t)(kb + y + j) * N + nb + x];
    __syncthreads();
#pragma unroll
    for (int j = 0; j < 32; j += 8)
        dst[(size_t)(nb + y + j) * K + kb + x] = to_tf32(t[x][y + j]);
}

// ---------------------------------------------------------------------------
// tf32 GEMM: 128x128 tile, 128 threads = 4 warps (2m x 2n), warp tile 64x64.
// 3-stage cp.async ring; ldmatrix fragment feed; 32 HMMA per kk-step per warp.
// C[M,N] = A[M,K] @ W[K,N] + bias[N]; W via pre-transposed g_wt[N][K].
// mode 0: A=g_xc, C=g_qkv (tf32-rounded store); mode 1: A=g_y, C=C_param.
// ---------------------------------------------------------------------------
#define SA 36                    // smem stride (floats); 144B rows, LDSM conflict-free
#define TBYTES (128 * SA * 4)    // 18432 per tile (A or B)
#define STAGEB (2 * TBYTES)      // 36864 per stage
#define GSTAGES 3
#define GSMEM (GSTAGES * STAGEB) // 110592

__global__ __launch_bounds__(128) void gemm_ls_kernel(
    const float* __restrict__ bias, float* __restrict__ C_param,
    int M, int N, int K, int mode)
{
    extern __shared__ float smg[];
    const float* A  = mode ? g_y : g_xc;
    const float* Bt = g_wt + (mode ? (size_t)3 * CDIM * CDIM : 0);
    float*       C  = mode ? C_param : g_qkv;

    const int tid = threadIdx.x, lane = tid & 31, wid = tid >> 5;
    const int wm = wid >> 1, wn = wid & 1;
    const int g = lane >> 2, q = lane & 3;
    const int m0 = blockIdx.y * 128, n0 = blockIdx.x * 128;
    const uint32_t sb = smem_u32(smg);

    const uint32_t a_off = a_frag_off(lane, SA);
    const uint32_t b_off = b_frag_off(lane, SA);

    float acc[4][8][4];
#pragma unroll
    for (int mt = 0; mt < 4; mt++)
#pragma unroll
        for (int nt = 0; nt < 8; nt++)
#pragma unroll
            for (int e = 0; e < 4; e++) acc[mt][nt][e] = 0.f;

    const int nc = K / 32;

    // prefetch stages 0 and 1
#pragma unroll
    for (int s = 0; s < 2; s++) {
        const int k0 = s * 32;
        const uint32_t st = sb + (uint32_t)(s * STAGEB);
#pragma unroll
        for (int i = 0; i < 8; i++) {
            const int f = tid + 128 * i;       // 0..1023
            const int row = f >> 3, c4 = f & 7;
            const uint32_t so = st + (uint32_t)((row * SA + c4 * 4) * 4);
            CP16(so, A + (size_t)(m0 + row) * K + k0 + c4 * 4);
            CP16(so + TBYTES, Bt + (size_t)(n0 + row) * K + k0 + c4 * 4);
        }
        CP_COMMIT();
    }

    for (int c = 0; c < nc; c++) {
        CP_WAIT(1);          // stage c resident
        __syncthreads();

        const uint32_t ab = sb + (uint32_t)((c % 3) * STAGEB);
        const uint32_t bbse = ab + TBYTES;
#pragma unroll
        for (int kk = 0; kk < 32; kk += 8) {
            uint32_t af[4][4], bf[4][4];
#pragma unroll
            for (int mt = 0; mt < 4; mt++)
                ldsm_x4(af[mt], ab + (uint32_t)(((wm * 64 + mt * 16) * SA + kk) * 4) + a_off);
#pragma unroll
            for (int pr = 0; pr < 4; pr++)
                ldsm_x4(bf[pr], bbse + (uint32_t)(((wn * 64 + pr * 16) * SA + kk) * 4) + b_off);
#pragma unroll
            for (int mt = 0; mt < 4; mt++)
#pragma unroll
                for (int nt = 0; nt < 8; nt++)
                    mma_tf32(acc[mt][nt], af[mt], bf[nt >> 1] + (nt & 1) * 2);
        }
        __syncthreads();     // all warps done with stage c before it is refilled

        if (c + 2 < nc) {
            const int k0 = (c + 2) * 32;
            const uint32_t st = sb + (uint32_t)(((c + 2) % 3) * STAGEB);
#pragma unroll
            for (int i = 0; i < 8; i++) {
                const int f = tid + 128 * i;
                const int row = f >> 3, c4 = f & 7;
                const uint32_t so = st + (uint32_t)((row * SA + c4 * 4) * 4);
                CP16(so, A + (size_t)(m0 + row) * K + k0 + c4 * 4);
                CP16(so + TBYTES, Bt + (size_t)(n0 + row) * K + k0 + c4 * 4);
            }
            CP_COMMIT();
        }
    }

    // epilogue
#pragma unroll
    for (int mt = 0; mt < 4; mt++) {
        int r0 = m0 + wm * 64 + mt * 16 + g;
#pragma unroll
        for (int nt = 0; nt < 8; nt++) {
            int cc = n0 + wn * 64 + nt * 8 + 2 * q;
            float b0 = bias[cc], b1 = bias[cc + 1];
            float v00 = acc[mt][nt][0] + b0, v01 = acc[mt][nt][1] + b1;
            float v10 = acc[mt][nt][2] + b0, v11 = acc[mt][nt][3] + b1;
            if (mode == 0) {
                v00 = to_tf32(v00); v01 = to_tf32(v01);
                v10 = to_tf32(v10); v11 = to_tf32(v11);
            }
            *(float2*)(C + (size_t)r0 * N + cc)       = make_float2(v00, v01);
            *(float2*)(C + (size_t)(r0 + 8) * N + cc) = make_float2(v10, v11);
        }
    }
}

// ---------------------------------------------------------------------------
// Flash attention, tf32 mma + ldmatrix. One block per (b,h,64-query tile);
// 128 threads = 4 warps (16 query rows each). Smem aliased:
//   buf0: Q (until q-frags hoisted) then K ; buf1: V then P ; buf2: Vt
// 52,224 B -> up to 4 blocks/SM. Heavy tiles (large qt) scheduled first.
// ---------------------------------------------------------------------------
#define SKA 68                       // stride (floats); LDSM conflict-free
#define TILE_F (64 * SKA)
#define TILE_B (TILE_F * 4)          // 17408
#define ASMEM (3 * TILE_B)           // 52224

__global__ __launch_bounds__(128, 3) void attn_ls_kernel()
{
    extern __shared__ float sm[];
    float* Vs = sm + TILE_F;         // aliased with Ps
    float* Vt = sm + 2 * TILE_F;

    const int qt = (gridDim.x - 1) - blockIdx.x;   // heavy-first
    const int h = blockIdx.y, b = blockIdx.z;
    const int tid = threadIdx.x, lane = tid & 31, w = tid >> 5;
    const int g = lane >> 2, q = lane & 3;
    const int q0 = qt * 64;

    const uint32_t sb = smem_u32(sm);
    const uint32_t sKQ = sb, sPV = sb + TILE_B, sVt = sb + 2 * TILE_B;

    const size_t rs = 3 * CDIM;
    const float* qb = g_qkv + (size_t)b * TLEN * rs + h * DH;
    const float* kb = qb + CDIM;
    const float* vb = qb + 2 * CDIM;

    const int lrow = tid >> 4;             // 0..7
    const int lcol = (tid & 15) * 4;       // 0..60
    const uint32_t aoff = a_frag_off(lane, SKA);
    const uint32_t boff = b_frag_off(lane, SKA);

    // ---- load Q into buf0, hoist fragments to registers (scaled) ----
#pragma unroll
    for (int p = 0; p < 8; p++) {
        uint32_t d = sKQ + (uint32_t)(((lrow + 8 * p) * SKA + lcol) * 4);
        CP16(d, qb + (size_t)(q0 + lrow + 8 * p) * rs + lcol);
    }
    CP_COMMIT(); CP_WAIT(0);
    __syncthreads();

    uint32_t qf[8][4];
#pragma unroll
    for (int kd = 0; kd < 8; kd++) {
        ldsm_x4(qf[kd], sKQ + (uint32_t)(((w * 16) * SKA + kd * 8) * 4) + aoff);
#pragma unroll
        for (int e = 0; e < 4; e++)
            qf[kd][e] = __float_as_uint(__uint_as_float(qf[kd][e]) * 0.125f);
    }

    float so[8][4];
    float mrow[2] = {-1e30f, -1e30f}, lsum[2] = {0.f, 0.f};
#pragma unroll
    for (int nt = 0; nt < 8; nt++)
#pragma unroll
        for (int e = 0; e < 4; e++) so[nt][e] = 0.f;

    for (int kt = 0; kt <= qt; kt++) {
        __syncthreads();   // q-frags hoisted / prior PV (Ps,Vt) reads complete
        {
            const int k0r = kt * 64;
#pragma unroll
            for (int p = 0; p < 8; p++) {
                uint32_t dk = sKQ + (uint32_t)(((lrow + 8 * p) * SKA + lcol) * 4);
                CP16(dk, kb + (size_t)(k0r + lrow + 8 * p) * rs + lcol);
                CP16(dk + TILE_B, vb + (size_t)(k0r + lrow + 8 * p) * rs + lcol); // -> Vs
            }
            CP_COMMIT(); CP_WAIT(0);
        }
        __syncthreads();

        // ---- transpose V: Vs[key][d] -> Vt[d][key] ----
        {
            const int td = tid & 63, tk = (tid >> 6) * 32;
#pragma unroll
            for (int i = 0; i < 8; i++) {
                const int k0 = tk + 4 * i;
                float4 v;
                v.x = Vs[(k0 + 0) * SKA + td];
                v.y = Vs[(k0 + 1) * SKA + td];
                v.z = Vs[(k0 + 2) * SKA + td];
                v.w = Vs[(k0 + 3) * SKA + td];
                *(float4*)&Vt[td * SKA + k0] = v;
            }
        }
        __syncthreads();   // Vt ready; Vs fully consumed -> buf1 reusable for P

        // ---- S = Q K^T ----
        float sc[8][4];
#pragma unroll
        for (int nt = 0; nt < 8; nt++)
#pragma unroll
            for (int e = 0; e < 4; e++) sc[nt][e] = 0.f;

#pragma unroll
        for (int kd = 0; kd < 8; kd++) {
            uint32_t bf[4][4];
#pragma unroll
            for (int pr = 0; pr < 4; pr++)
                ldsm_x4(bf[pr], sKQ + (uint32_t)(((pr * 16) * SKA + kd * 8) * 4) + boff);
#pragma unroll
            for (int nt = 0; nt < 8; nt++)
                mma_tf32(sc[nt], qf[kd], bf[nt >> 1] + (nt & 1) * 2);
        }

        // ---- causal mask on diagonal tile ----
        if (kt == qt) {
            const int r0 = w * 16 + g, r1 = r0 + 8;
#pragma unroll
            for (int nt = 0; nt < 8; nt++) {
                const int c = nt * 8 + 2 * q;
                if (c     > r0) sc[nt][0] = -1e30f;
                if (c + 1 > r0) sc[nt][1] = -1e30f;
                if (c     > r1) sc[nt][2] = -1e30f;
                if (c + 1 > r1) sc[nt][3] = -1e30f;
            }
        }

        // ---- online softmax (2 rows per thread) ----
        float mx0 = -1e30f, mx1 = -1e30f;
#pragma unroll
        for (int nt = 0; nt < 8; nt++) {
            mx0 = fmaxf(mx0, fmaxf(sc[nt][0], sc[nt][1]));
            mx1 = fmaxf(mx1, fmaxf(sc[nt][2], sc[nt][3]));
        }
        mx0 = fmaxf(mx0, __shfl_xor_sync(0xffffffffu, mx0, 1));
        mx0 = fmaxf(mx0, __shfl_xor_sync(0xffffffffu, mx0, 2));
        mx1 = fmaxf(mx1, __shfl_xor_sync(0xffffffffu, mx1, 1));
        mx1 = fmaxf(mx1, __shfl_xor_sync(0xffffffffu, mx1, 2));

        const float mn0 = fmaxf(mrow[0], mx0);
        const float mn1 = fmaxf(mrow[1], mx1);
        const float al0 = __expf(mrow[0] - mn0);
        const float al1 = __expf(mrow[1] - mn1);
        mrow[0] = mn0; mrow[1] = mn1;

        float s0 = 0.f, s1 = 0.f;
#pragma unroll
        for (int nt = 0; nt < 8; nt++) {
            sc[nt][0] = __expf(sc[nt][0] - mn0); s0 += sc[nt][0];
            sc[nt][1] = __expf(sc[nt][1] - mn0); s0 += sc[nt][1];
            sc[nt][2] = __expf(sc[nt][2] - mn1); s1 += sc[nt][2];
            sc[nt][3] = __expf(sc[nt][3] - mn1); s1 += sc[nt][3];
        }
        s0 += __shfl_xor_sync(0xffffffffu, s0, 1);
        s0 += __shfl_xor_sync(0xffffffffu, s0, 2);
        s1 += __shfl_xor_sync(0xffffffffu, s1, 1);
        s1 += __shfl_xor_sync(0xffffffffu, s1, 2);
        lsum[0] = lsum[0] * al0 + s0;
        lsum[1] = lsum[1] * al1 + s1;

#pragma unroll
        for (int nt = 0; nt < 8; nt++) {
            so[nt][0] *= al0; so[nt][1] *= al0;
            so[nt][2] *= al1; so[nt][3] *= al1;
        }

        // ---- store P (tf32) into buf1 (ex-Vs) for a-frag reload ----
        {
            float* Ps = Vs;   // alias
            const int r0 = w * 16 + g;
#pragma unroll
            for (int nt = 0; nt < 8; nt++) {
                const int c = nt * 8 + 2 * q;
                *(float2*)&Ps[r0 * SKA + c] =
                    make_float2(to_tf32(sc[nt][0]), to_tf32(sc[nt][1]));
                *(float2*)&Ps[(r0 + 8) * SKA + c] =
                    make_float2(to_tf32(sc[nt][2]), to_tf32(sc[nt][3]));
            }
        }
        __syncwarp();   // P rows owned/read by this warp only

        // ---- O += P V ----
#pragma unroll
        for (int kd = 0; kd < 8; kd++) {
            uint32_t pf[4], bf[4][4];
            ldsm_x4(pf, sPV + (uint32_t)(((w * 16) * SKA + kd * 8) * 4) + aoff);
#pragma unroll
            for (int pr = 0; pr < 4; pr++)
                ldsm_x4(bf[pr], sVt + (uint32_t)(((pr * 16) * SKA + kd * 8) * 4) + boff);
#pragma unroll
            for (int nt = 0; nt < 8; nt++)
                mma_tf32(so[nt], pf, bf[nt >> 1] + (nt & 1) * 2);
        }
    }

    // ---- normalize + store y (tf32 for GEMM2 consumption) ----
    {
        const float inv0 = 1.f / lsum[0];
        const float inv1 = 1.f / lsum[1];
        const int r0 = q0 + w * 16 + g;
        float* yb = g_y + (size_t)b * TLEN * CDIM + h * DH;
#pragma unroll
        for (int nt = 0; nt < 8; nt++) {
            const int c = nt * 8 + 2 * q;
            *(float2*)(yb + (size_t)r0 * CDIM + c) =
                make_float2(to_tf32(so[nt][0] * inv0), to_tf32(so[nt][1] * inv0));
            *(float2*)(yb + (size_t)(r0 + 8) * CDIM + c) =
                make_float2(to_tf32(so[nt][2] * inv1), to_tf32(so[nt][3] * inv1));
        }
    }
}

// ---------------------------------------------------------------------------
extern "C" void kernel_launch(void* const* d_in, const int* in_sizes, int n_in,
                              void* d_out, int out_size)
{
    const float* x      = (const float*)d_in[0];
    const float* W_attn = (const float*)d_in[1];
    const float* b_attn = (const float*)d_in[2];
    const float* W_proj = (const float*)d_in[3];
    const float* b_proj = (const float*)d_in[4];
    float* out = (float*)d_out;

    cudaFuncSetAttribute(gemm_ls_kernel, cudaFuncAttributeMaxDynamicSharedMemorySize, GSMEM);
    cudaFuncSetAttribute(attn_ls_kernel, cudaFuncAttributeMaxDynamicSharedMemorySize, ASMEM);

    // 0) pre-convert x; transpose+convert weights
    cvt_kernel<<<(MROWS * CDIM) / (256 * 4), 256>>>(x);
    {
        dim3 tb(32, 8);
        transpose_kernel<<<dim3((3 * CDIM) / 32, CDIM / 32), tb>>>(W_attn, CDIM, 3 * CDIM, 0);
        transpose_kernel<<<dim3(CDIM / 32, CDIM / 32), tb>>>(W_proj, CDIM, CDIM, 1);
    }
    // 1) qkv = x @ W_attn + b_attn (tf32-rounded)
    {
        dim3 grid((3 * CDIM) / 128, MROWS / 128);
        gemm_ls_kernel<<<grid, 128, GSMEM>>>(b_attn, nullptr, MROWS, 3 * CDIM, CDIM, 0);
    }
    // 2) flash attention -> g_y (tf32-rounded)
    {
        dim3 grid(TLEN / 64, HN, BSZ);
        attn_ls_kernel<<<grid, 128, ASMEM>>>();
    }
    // 3) out = y @ W_proj + b_proj
    {
        dim3 grid(CDIM / 128, MROWS / 128);
        gemm_ls_kernel<<<grid, 128, GSMEM>>>(b_proj, out, MROWS, CDIM, CDIM, 1);
    }
}